// round 16
// baseline (speedup 1.0000x reference)
#include <cuda_runtime.h>
#include <cuda_bf16.h>

#define QN 16384
#define SN 16384
#define FD 64
#define HN 32
#define EN 393216
#define CAP 64           // bucket capacity; P(count>64) ~ 1e-7 for Poisson(24)

typedef unsigned long long ull;

// ---------------- packed f32x2 + wide-load helpers ----------------
__device__ __forceinline__ ull pk2(float lo, float hi) {
    ull r; asm("mov.b64 %0,{%1,%2};" : "=l"(r) : "f"(lo), "f"(hi)); return r;
}
__device__ __forceinline__ void upk2(ull v, float& lo, float& hi) {
    asm("mov.b64 {%0,%1},%2;" : "=f"(lo), "=f"(hi) : "l"(v));
}
__device__ __forceinline__ ull add2(ull a, ull b) {
    ull r; asm("add.rn.f32x2 %0,%1,%2;" : "=l"(r) : "l"(a), "l"(b)); return r;
}
__device__ __forceinline__ void lds2(ull& a, ull& b, unsigned addr) {
    asm volatile("ld.shared.v2.u64 {%0,%1},[%2];" : "=l"(a), "=l"(b) : "r"(addr));
}
__device__ __forceinline__ void sts2(unsigned a, ull x, ull y) {
    asm volatile("st.shared.v2.u64 [%0],{%1,%2};" :: "r"(a), "l"(x), "l"(y) : "memory");
}
__device__ __forceinline__ void ldg4(ull& a, ull& b, ull& c, ull& d, const void* p) {
    asm volatile("ld.global.nc.v4.u64 {%0,%1,%2,%3},[%4];"
                 : "=l"(a), "=l"(b), "=l"(c), "=l"(d) : "l"(p));
}
__device__ __forceinline__ void stg4(void* p, ull a, ull b, ull c, ull d) {
    asm volatile("st.global.v4.u64 [%0],{%1,%2,%3,%4};"
                 :: "l"(p), "l"(a), "l"(b), "l"(c), "l"(d) : "memory");
}
__device__ __forceinline__ float ldsf(unsigned a) {
    float v; asm volatile("ld.shared.f32 %0,[%1];" : "=f"(v) : "r"(a)); return v;
}
__device__ __forceinline__ void lds64f(float& x, float& y, unsigned a) {
    asm volatile("ld.shared.v2.f32 {%0,%1},[%2];" : "=f"(x), "=f"(y) : "r"(a));
}
__device__ __forceinline__ void stsv2(unsigned a, float x, float y) {
    asm volatile("st.shared.v2.f32 [%0],{%1,%2};" :: "r"(a), "f"(x), "f"(y) : "memory");
}
__device__ __forceinline__ unsigned su32(const void* p) {
    unsigned r;
    asm("{ .reg .u64 t; cvta.to.shared.u64 t, %1; cvt.u32.u64 %0, t; }" : "=r"(r) : "l"(p));
    return r;
}
// m16n8k8 tf32 MMA (raw f32 bits -> tf32 truncation)
__device__ __forceinline__ void mma8(float& c0, float& c1, float& c2, float& c3,
                                     float a0, float a1, float a2, float a3,
                                     float b0, float b1) {
    asm volatile("mma.sync.aligned.m16n8k8.row.col.f32.tf32.tf32.f32 "
                 "{%0,%1,%2,%3},{%4,%5,%6,%7},{%8,%9},{%0,%1,%2,%3};"
                 : "+f"(c0), "+f"(c1), "+f"(c2), "+f"(c3)
                 : "r"(__float_as_uint(a0)), "r"(__float_as_uint(a1)),
                   "r"(__float_as_uint(a2)), "r"(__float_as_uint(a3)),
                   "r"(__float_as_uint(b0)), "r"(__float_as_uint(b1)));
}
// repack 8 consecutive floats (f0..f7 in 4 ulls) into interleaved order
// [f0,f4, f1,f5, f2,f6, f3,f7] and store 32B at smem addr
__device__ __forceinline__ void sts_perm(unsigned dst, ull a, ull b, ull c, ull d) {
    float f0,f1,f2,f3,f4,f5,f6,f7;
    upk2(a, f0, f1); upk2(b, f2, f3); upk2(c, f4, f5); upk2(d, f6, f7);
    sts2(dst,      pk2(f0, f4), pk2(f1, f5));
    sts2(dst + 16, pk2(f2, f6), pk2(f3, f7));
}

// ---------------- static device scratch ----------------
__device__ __align__(128) float g_xK [QN*FD];
__device__ __align__(128) float g_xV [QN*FD];
__device__ __align__(128) float g_xQ1[QN*FD];
__device__ __align__(128) float g_xMk[QN*FD];
__device__ __align__(128) float g_sQ2 [SN*FD];
__device__ __align__(128) float g_sidK[SN*FD];
__device__ __align__(128) float g_sidV[SN*FD];
__device__ __align__(128) float g_W1K[FD*FD], g_W1V[FD*FD], g_MK[FD*FD], g_MV[FD*FD], g_cV[FD];

__device__ int g_scur[2][SN];
__device__ int g_qcur[2][QN];
__device__ int g_eq_by_s[2][SN*CAP];
__device__ int g_sid_by_q[2][QN*CAP];

__device__ __align__(128) float g_agg[2][(size_t)QN*CAP*FD];
__device__ float g_chO[2][QN*FD];

// ---------------- init: tiny weight products + cursor zeroing ----------------
__global__ void __launch_bounds__(256) k_init(const float* __restrict__ W_fuse,
                                              const float* __restrict__ W_K2,
                                              const float* __restrict__ W_V2,
                                              const float* __restrict__ b_fuse,
                                              const float* __restrict__ b_V2) {
    if (blockIdx.x < 64) {
        int i = blockIdx.x, j = threadIdx.x;
        if (j >= 64) return;
        float s1k = 0.f, s1v = 0.f, smk = 0.f, smv = 0.f;
        for (int k = 0; k < FD; k++) {
            float wf1 = W_fuse[i*FD + k];
            float wf2 = W_fuse[(FD + i)*FD + k];
            float wk2 = W_K2[k*FD + j];
            float wv2 = W_V2[k*FD + j];
            s1k = fmaf(wf1, wk2, s1k);
            s1v = fmaf(wf1, wv2, s1v);
            smk = fmaf(wf2, wk2, smk);
            smv = fmaf(wf2, wv2, smv);
        }
        g_W1K[i*FD + j] = s1k; g_W1V[i*FD + j] = s1v;
        g_MK [i*FD + j] = smk; g_MV [i*FD + j] = smv;
        if (i == 0) {
            float c = 0.f;
            for (int k = 0; k < FD; k++) c = fmaf(b_fuse[k], W_V2[k*FD + j], c);
            g_cV[j] = c + b_V2[j];
        }
    } else {
        int i = (blockIdx.x - 64) * 256 + threadIdx.x;
        g_scur[0][i] = 0; g_scur[1][i] = 0;
        g_qcur[0][i] = 0; g_qcur[1][i] = 0;
    }
}

// ---------------- fused prep: 7 row-GEMMs in one launch ----------------
__global__ void __launch_bounds__(128) k_prep(const float* __restrict__ x,
                                              const float* __restrict__ s_emb,
                                              const float* __restrict__ W_Q,
                                              const float* __restrict__ b_Q,
                                              const float* __restrict__ W_K,
                                              const float* __restrict__ b_K,
                                              const float* __restrict__ W_V,
                                              const float* __restrict__ b_V) {
    int job = blockIdx.z, cq = blockIdx.y, t = threadIdx.x;
    const float* A; const float* B; const float* bias = b_Q; float* C;
    int transB = 0, addBias = 0;
    switch (job) {
        case 0: A = x;     B = W_K;          bias = b_K; C = g_xK;   addBias = 1; break;
        case 1: A = x;     B = W_V;          bias = b_V; C = g_xV;   addBias = 1; break;
        case 2: A = x;     B = W_Q;                      C = g_xQ1;               break;
        case 3: A = x;     B = g_MK;                     C = g_xMk;  transB = 1;  break;
        case 4: A = s_emb; B = W_Q + FD*FD;  bias = b_Q; C = g_sQ2;  addBias = 1; break;
        case 5: A = s_emb; B = g_W1K;                    C = g_sidK;              break;
        default:A = s_emb; B = g_W1V;                    C = g_sidV;              break;
    }
    __shared__ float Bs[FD*16];
    for (int idx = t; idx < FD*16; idx += 128) {
        int k = idx >> 4, j = idx & 15;
        Bs[idx] = transB ? B[(cq*16 + j)*FD + k] : B[k*FD + cq*16 + j];
    }
    __syncthreads();
    int r = blockIdx.x * 128 + t;
    float acc[16];
#pragma unroll
    for (int j = 0; j < 16; j++) acc[j] = addBias ? bias[cq*16 + j] : 0.f;
    const float4* a4 = (const float4*)(A + (size_t)r * FD);
#pragma unroll
    for (int k4 = 0; k4 < 16; k4++) {
        float4 av = a4[k4];
        const float* bp = Bs + k4*4*16;
#pragma unroll
        for (int j = 0; j < 16; j++) acc[j] = fmaf(av.x, bp[j],      acc[j]);
#pragma unroll
        for (int j = 0; j < 16; j++) acc[j] = fmaf(av.y, bp[16 + j], acc[j]);
#pragma unroll
        for (int j = 0; j < 16; j++) acc[j] = fmaf(av.z, bp[32 + j], acc[j]);
#pragma unroll
        for (int j = 0; j < 16; j++) acc[j] = fmaf(av.w, bp[48 + j], acc[j]);
    }
    float4* c4 = (float4*)(C + (size_t)r * FD + cq*16);
#pragma unroll
    for (int j4 = 0; j4 < 4; j4++)
        c4[j4] = make_float4(acc[4*j4], acc[4*j4+1], acc[4*j4+2], acc[4*j4+3]);
}

// ---------------- s-side bucketing ----------------
__global__ void k_bucket(const int* __restrict__ sp, const int* __restrict__ qp,
                         const int* __restrict__ sn, const int* __restrict__ qn) {
    int ch = blockIdx.z;
    int i = blockIdx.x * blockDim.x + threadIdx.x;
    if (i >= EN) return;
    const int* es = ch ? sn : sp;
    const int* eq = ch ? qn : qp;
    int s = es[i], q = eq[i];
    int ps = atomicAdd(&g_scur[ch][s], 1);
    if (ps < CAP) g_eq_by_s[ch][s*CAP + ps] = q;
}

// ---------------- pass A: tf32 HMMA, feat-interleaved Q/K, single K/V buffer ----------------
#define PADW 68
#define PA_WSM (2*32*PADW + 64)   // buf + qS + sQ2 = 4416 floats/warp (17.7 KB)
__global__ void __launch_bounds__(64, 6) k_passA(const int* __restrict__ hqp,
                                                 const int* __restrict__ hcp,
                                                 const int* __restrict__ hqn,
                                                 const int* __restrict__ hcn) {
    extern __shared__ float smA[];
    int ch = blockIdx.z;
    const int* hist_qid = ch ? hqn : hqp;
    const int* hist_cnt = ch ? hcn : hcp;
    const int* eqs  = g_eq_by_s[ch];
    int* qcur = g_qcur[ch];
    int* sidq = g_sid_by_q[ch];
    float* aggc = g_agg[ch];

    int lane = threadIdx.x & 31;
    int w    = threadIdx.x >> 5;
    int s    = blockIdx.x * 2 + w;
    float* buf = smA + w * PA_WSM;   // K (feat-permuted) during score, V (raw) during agg
    float* qS  = buf + 32*PADW;      // Q staging (feat-permuted); reused for P and agg frags
    float* sQ2 = qS + 32*PADW;       // 64 floats

    int cnt = hist_cnt[s];
    cnt = min(max(cnt, 0), HN);
    int cpad = (cnt + 7) & ~7;
    int nth  = cpad >> 3;            // 8-wide history tiles (0..4), warp-uniform

    unsigned bufb = su32(buf);
    unsigned qSb  = su32(qS);
    unsigned pSb  = qSb;
    unsigned sQ2b = su32(sQ2);

    int sub = lane >> 3;             // 0..3
    int col = (lane & 7) * 32;       // byte offset within 256B row

    int hid_l = (lane < cnt) ? hist_qid[s*HN + lane] : 0;

    sQ2[lane]      = g_sQ2[s*FD + lane];
    sQ2[lane + 32] = g_sQ2[s*FD + lane + 32];

    int ecnt = min(g_scur[ch][s], CAP);
    if (ecnt == 0) return;
    int base = s * CAP;

    int gid = lane >> 2, tid = lane & 3;   // MMA fragment coords

    int ii_n = (lane < ecnt) ? lane : (ecnt - 1);
    int qid_n = eqs[base + ii_n];

    for (int b0e = 0; b0e < ecnt; b0e += 32) {
        int i = b0e + lane;
        bool act = i < ecnt;
        int qid = qid_n;
        int in = b0e + 32 + lane;
        if (in < ecnt) qid_n = eqs[base + in];

        // ---- load K (feat-permuted) into buf + stage q (feat-permuted) into qS ----
#pragma unroll
        for (int it = 0; it < 8; it++) {
            int row = it*4 + sub;
            int hid = __shfl_sync(0xffffffffu, hid_l, row);
            unsigned kdst = bufb + row*(PADW*4) + col;
            if (row < cnt) {
                ull a, b, c, d;
                ldg4(a, b, c, d, (const char*)(g_xK + (size_t)hid * FD) + col);
                sts_perm(kdst, a, b, c, d);
            } else if (row < cpad) {
                sts2(kdst, 0ull, 0ull); sts2(kdst + 16, 0ull, 0ull);
            }
        }
#pragma unroll
        for (int it = 0; it < 8; it++) {
            int row = it*4 + sub;
            int qr = __shfl_sync(0xffffffffu, qid, row);
            ull a, b, c, d, e, f, g2, h2;
            ldg4(a, b, c, d, (const char*)(g_xQ1 + (size_t)qr * FD) + col);
            lds2(e, f, sQ2b + col);
            lds2(g2, h2, sQ2b + col + 16);
            a = add2(a, e); b = add2(b, f); c = add2(c, g2); d = add2(d, h2);
            sts_perm(qSb + row*(PADW*4) + col, a, b, c, d);
        }
        __syncwarp();

        // ---- load Q A-fragments via lds64 (perm makes (a0,a2)/(a1,a3) adjacent) ----
        float Af[2][8][4];
#pragma unroll
        for (int mt = 0; mt < 2; mt++)
#pragma unroll
            for (int kt = 0; kt < 8; kt++) {
                unsigned a = qSb + ((mt*16 + gid)*PADW + kt*8 + 2*tid) * 4;
                lds64f(Af[mt][kt][0], Af[mt][kt][2], a);
                lds64f(Af[mt][kt][1], Af[mt][kt][3], a + 8*PADW*4);
            }

        // ---- score GEMM: S = Q @ K^T (B-frag pair via one lds64) ----
        float cS[2][4][4];
#pragma unroll
        for (int nt = 0; nt < 4; nt++) {
            if (nt >= nth) break;
#pragma unroll
            for (int mt = 0; mt < 2; mt++)
#pragma unroll
                for (int r = 0; r < 4; r++) cS[mt][nt][r] = 0.f;
#pragma unroll
            for (int kt = 0; kt < 8; kt++) {
                float b0, b1;
                lds64f(b0, b1, bufb + ((nt*8 + gid)*PADW + kt*8 + 2*tid) * 4);
                mma8(cS[0][nt][0], cS[0][nt][1], cS[0][nt][2], cS[0][nt][3],
                     Af[0][kt][0], Af[0][kt][1], Af[0][kt][2], Af[0][kt][3], b0, b1);
                mma8(cS[1][nt][0], cS[1][nt][1], cS[1][nt][2], cS[1][nt][3],
                     Af[1][kt][0], Af[1][kt][1], Af[1][kt][2], Af[1][kt][3], b0, b1);
            }
        }
        __syncwarp();   // K reads complete; buf free for V

        // ---- load V (raw layout) into buf ----
#pragma unroll
        for (int it = 0; it < 8; it++) {
            int row = it*4 + sub;
            int hid = __shfl_sync(0xffffffffu, hid_l, row);
            unsigned vdst = bufb + row*(PADW*4) + col;
            if (row < cnt) {
                ull a, b, c, d;
                ldg4(a, b, c, d, (const char*)(g_xV + (size_t)hid * FD) + col);
                sts2(vdst, a, b); sts2(vdst + 16, c, d);
            } else if (row < cpad) {
                sts2(vdst, 0ull, 0ull); sts2(vdst + 16, 0ull, 0ull);
            }
        }

        // ---- masked exp + per-row denominators ----
        float den00 = 0.f, den01 = 0.f, den10 = 0.f, den11 = 0.f;
#pragma unroll
        for (int nt = 0; nt < 4; nt++) {
            if (nt >= nth) break;
            int h0 = nt*8 + 2*tid, h1 = h0 + 1;
            float e0 = (h0 < cnt) ? __expf(cS[0][nt][0] * 0.125f) : 0.f;
            float e1 = (h1 < cnt) ? __expf(cS[0][nt][1] * 0.125f) : 0.f;
            float e2 = (h0 < cnt) ? __expf(cS[0][nt][2] * 0.125f) : 0.f;
            float e3 = (h1 < cnt) ? __expf(cS[0][nt][3] * 0.125f) : 0.f;
            cS[0][nt][0] = e0; cS[0][nt][1] = e1; cS[0][nt][2] = e2; cS[0][nt][3] = e3;
            den00 += e0 + e1; den01 += e2 + e3;
            float f0 = (h0 < cnt) ? __expf(cS[1][nt][0] * 0.125f) : 0.f;
            float f1 = (h1 < cnt) ? __expf(cS[1][nt][1] * 0.125f) : 0.f;
            float f2 = (h0 < cnt) ? __expf(cS[1][nt][2] * 0.125f) : 0.f;
            float f3 = (h1 < cnt) ? __expf(cS[1][nt][3] * 0.125f) : 0.f;
            cS[1][nt][0] = f0; cS[1][nt][1] = f1; cS[1][nt][2] = f2; cS[1][nt][3] = f3;
            den10 += f0 + f1; den11 += f2 + f3;
        }
#pragma unroll
        for (int o = 1; o <= 2; o <<= 1) {
            den00 += __shfl_xor_sync(0xffffffffu, den00, o);
            den01 += __shfl_xor_sync(0xffffffffu, den01, o);
            den10 += __shfl_xor_sync(0xffffffffu, den10, o);
            den11 += __shfl_xor_sync(0xffffffffu, den11, o);
        }
        float inv00 = (den00 > 0.f) ? 1.f/den00 : 0.f;
        float inv01 = (den01 > 0.f) ? 1.f/den01 : 0.f;
        float inv10 = (den10 > 0.f) ? 1.f/den10 : 0.f;
        float inv11 = (den11 > 0.f) ? 1.f/den11 : 0.f;

        // ---- store normalized P into qS (unpermuted h-cols) ----
#pragma unroll
        for (int nt = 0; nt < 4; nt++) {
            if (nt >= nth) break;
            unsigned p0 = pSb + (gid*PADW + nt*8 + 2*tid) * 4;
            stsv2(p0,              cS[0][nt][0]*inv00, cS[0][nt][1]*inv00);
            stsv2(p0 + 8*PADW*4,   cS[0][nt][2]*inv01, cS[0][nt][3]*inv01);
            unsigned p1 = pSb + ((16 + gid)*PADW + nt*8 + 2*tid) * 4;
            stsv2(p1,              cS[1][nt][0]*inv10, cS[1][nt][1]*inv10);
            stsv2(p1 + 8*PADW*4,   cS[1][nt][2]*inv11, cS[1][nt][3]*inv11);
        }
        __syncwarp();   // P visible + V stores visible

        // ---- load P A-fragments ----
        float Ap[2][4][4];
#pragma unroll
        for (int mt = 0; mt < 2; mt++)
#pragma unroll
            for (int kt = 0; kt < 4; kt++) {
                if (kt >= nth) break;
                unsigned a = pSb + ((mt*16 + gid)*PADW + kt*8 + tid) * 4;
                Ap[mt][kt][0] = ldsf(a);
                Ap[mt][kt][1] = ldsf(a + 8*PADW*4);
                Ap[mt][kt][2] = ldsf(a + 16);
                Ap[mt][kt][3] = ldsf(a + 8*PADW*4 + 16);
            }
        __syncwarp();   // Ap loaded before agg frags overwrite pS

        // ---- claim q-side slot ----
        int rq = -1;
        if (act) {
            int slot = atomicAdd(&qcur[qid], 1);
            if (slot < CAP) { rq = qid*CAP + slot; sidq[rq] = s; }
        }

        // ---- agg GEMM: agg = P @ V; B loads hoisted across both m-tiles ----
        float cA[2][8][4];
#pragma unroll
        for (int mt = 0; mt < 2; mt++)
#pragma unroll
            for (int n2 = 0; n2 < 8; n2++)
#pragma unroll
                for (int r = 0; r < 4; r++) cA[mt][n2][r] = 0.f;
#pragma unroll
        for (int kt = 0; kt < 4; kt++) {
            if (kt >= nth) break;
#pragma unroll
            for (int n2 = 0; n2 < 8; n2++) {
                unsigned vb = bufb + ((kt*8 + tid)*PADW + n2*8 + gid) * 4;
                float b0 = ldsf(vb);
                float b1 = ldsf(vb + 4*PADW*4);
                mma8(cA[0][n2][0], cA[0][n2][1], cA[0][n2][2], cA[0][n2][3],
                     Ap[0][kt][0], Ap[0][kt][1], Ap[0][kt][2], Ap[0][kt][3], b0, b1);
                mma8(cA[1][n2][0], cA[1][n2][1], cA[1][n2][2], cA[1][n2][3],
                     Ap[1][kt][0], Ap[1][kt][1], Ap[1][kt][2], Ap[1][kt][3], b0, b1);
            }
        }
#pragma unroll
        for (int mt = 0; mt < 2; mt++)
#pragma unroll
            for (int n2 = 0; n2 < 8; n2++) {
                unsigned p0 = pSb + ((mt*16 + gid)*PADW + n2*8 + 2*tid) * 4;
                stsv2(p0, cA[mt][n2][0], cA[mt][n2][1]);
                unsigned p1 = pSb + ((mt*16 + 8 + gid)*PADW + n2*8 + 2*tid) * 4;
                stsv2(p1, cA[mt][n2][2], cA[mt][n2][3]);
            }
        __syncwarp();

        // ---- cooperative agg store: 8 lanes per row ----
#pragma unroll
        for (int it = 0; it < 8; it++) {
            int row = it*4 + sub;
            int r = __shfl_sync(0xffffffffu, rq, row);
            if (r >= 0) {
                ull a, b, c, d;
                lds2(a, b, pSb + row*(PADW*4) + col);
                lds2(c, d, pSb + row*(PADW*4) + col + 16);
                stg4((char*)(aggc + (size_t)r * FD) + col, a, b, c, d);
            }
        }
        __syncwarp();
    }
}

// ---------------- pass B: logits + segment softmax + finalize, 2-edge unroll ----------------
__global__ void __launch_bounds__(256) k_passB(const float* __restrict__ x) {
    __shared__ float MVs[FD*FD];
    __shared__ float cVs[FD];
    __shared__ float rb[8][FD];
    int ch = blockIdx.z;
    int t = threadIdx.x;
    for (int i = t; i < FD*FD; i += 256) MVs[i] = g_MV[i];
    if (t < FD) cVs[t] = g_cV[t];
    __syncthreads();
    int lane = t & 31, w = t >> 5;
    int q = blockIdx.x * 8 + w;
    int qcnt = min(g_qcur[ch][q], CAP);
    int base = q * CAP;
    const int*   sidq = g_sid_by_q[ch];
    const float* aggc = g_agg[ch];

    float xq0 = x[q*FD + lane],      xq1 = x[q*FD + 32 + lane];
    float mk0 = g_xMk[q*FD + lane],  mk1 = g_xMk[q*FD + 32 + lane];

    float d = 0.f, P0 = 0.f, P1 = 0.f, R0 = 0.f, R1 = 0.f;
    int j = 0;
    for (; j + 1 < qcnt; j += 2) {
        int s0 = sidq[base + j], s1 = sidq[base + j + 1];
        const float* agA = aggc + (size_t)(base + j) * FD;
        const float* agB = aggc + (size_t)(base + j + 1) * FD;
        float a00 = agA[lane], a01 = agA[32 + lane];
        float a10 = agB[lane], a11 = agB[32 + lane];
        const float* svA = g_sidV + (size_t)s0 * FD;
        const float* svB = g_sidV + (size_t)s1 * FD;
        float v00 = svA[lane], v01 = svA[32 + lane];
        float v10 = svB[lane], v11 = svB[32 + lane];
        const float* skA = g_sidK + (size_t)s0 * FD;
        const float* skB = g_sidK + (size_t)s1 * FD;
        float k00 = skA[lane], k01 = skA[32 + lane];
        float k10 = skB[lane], k11 = skB[32 + lane];

        float p0 = xq0*k00 + xq1*k01 + mk0*a00 + mk1*a01;
        float p1 = xq0*k10 + xq1*k11 + mk0*a10 + mk1*a11;
#pragma unroll
        for (int o = 16; o > 0; o >>= 1) {
            p0 += __shfl_xor_sync(0xffffffffu, p0, o);
            p1 += __shfl_xor_sync(0xffffffffu, p1, o);
        }
        float e0 = __expf(p0 * 0.125f);
        float e1 = __expf(p1 * 0.125f);
        d += e0 + e1;
        P0 = fmaf(e0, v00, fmaf(e1, v10, P0));
        P1 = fmaf(e0, v01, fmaf(e1, v11, P1));
        R0 = fmaf(e0, a00, fmaf(e1, a10, R0));
        R1 = fmaf(e0, a01, fmaf(e1, a11, R1));
    }
    if (j < qcnt) {
        int s0 = sidq[base + j];
        const float* ag = aggc + (size_t)(base + j) * FD;
        float a0 = ag[lane], a1 = ag[32 + lane];
        const float* sv = g_sidV + (size_t)s0 * FD;
        float v0 = sv[lane], v1 = sv[32 + lane];
        const float* sk = g_sidK + (size_t)s0 * FD;
        float k0 = sk[lane], k1 = sk[32 + lane];
        float p0 = xq0*k0 + xq1*k1 + mk0*a0 + mk1*a1;
#pragma unroll
        for (int o = 16; o > 0; o >>= 1) p0 += __shfl_xor_sync(0xffffffffu, p0, o);
        float e0 = __expf(p0 * 0.125f);
        d += e0;
        P0 = fmaf(e0, v0, P0);
        P1 = fmaf(e0, v1, P1);
        R0 = fmaf(e0, a0, R0);
        R1 = fmaf(e0, a1, R1);
    }
    rb[w][lane] = R0; rb[w][32 + lane] = R1;
    __syncwarp();
    float o0 = fmaf(d, cVs[lane],      P0);
    float o1 = fmaf(d, cVs[32 + lane], P1);
#pragma unroll
    for (int k = 0; k < FD; k++) {
        float rk = rb[w][k];
        o0 = fmaf(rk, MVs[k*FD + lane],      o0);
        o1 = fmaf(rk, MVs[k*FD + 32 + lane], o1);
    }
    float inv = 1.f / fmaxf(d, 1e-9f);
    float* o = &g_chO[ch][(size_t)q * FD];
    o[lane]      = o0 * inv;
    o[32 + lane] = o1 * inv;
}

// ---------------- final projection ----------------
__global__ void __launch_bounds__(128) k_project(const float* __restrict__ Wp,
                                                 const float* __restrict__ bp,
                                                 float* __restrict__ out) {
    __shared__ float W1s[FD*FD], W2s[FD*FD];
    int t = threadIdx.x;
    for (int i = t; i < FD*FD; i += 128) { W1s[i] = Wp[i]; W2s[i] = Wp[FD*FD + i]; }
    __syncthreads();
    int q = blockIdx.x * 128 + t;
    float acc[FD];
#pragma unroll
    for (int j = 0; j < FD; j++) acc[j] = bp[j];
    const float* pr = &g_chO[0][(size_t)q * FD];
    const float* nr = &g_chO[1][(size_t)q * FD];
    for (int k = 0; k < FD; k++) {
        float pv = pr[k], nv = nr[k];
#pragma unroll
        for (int j = 0; j < FD; j++)
            acc[j] = fmaf(pv, W1s[k*FD + j], fmaf(nv, W2s[k*FD + j], acc[j]));
    }
    float* o = out + (size_t)q * FD;
#pragma unroll
    for (int j = 0; j < FD; j++) o[j] = acc[j];
}

// ---------------- launch ----------------
extern "C" void kernel_launch(void* const* d_in, const int* in_sizes, int n_in,
                              void* d_out, int out_size) {
    const float* x      = (const float*)d_in[0];
    const float* s_emb  = (const float*)d_in[1];
    const float* W_Q    = (const float*)d_in[2];
    const float* b_Q    = (const float*)d_in[3];
    const float* W_K    = (const float*)d_in[4];
    const float* b_K    = (const float*)d_in[5];
    const float* W_V    = (const float*)d_in[6];
    const float* b_V    = (const float*)d_in[7];
    const float* W_fuse = (const float*)d_in[8];
    const float* b_fuse = (const float*)d_in[9];
    const float* W_K2   = (const float*)d_in[10];
    const float* W_V2   = (const float*)d_in[12];
    const float* b_V2   = (const float*)d_in[13];
    const float* W_proj = (const float*)d_in[14];
    const float* b_proj = (const float*)d_in[15];
    const int* hist_qid_pos = (const int*)d_in[18];
    const int* hist_cnt_pos = (const int*)d_in[19];
    const int* hist_qid_neg = (const int*)d_in[20];
    const int* hist_cnt_neg = (const int*)d_in[21];
    const int* edge_sid_pos = (const int*)d_in[22];
    const int* edge_qid_pos = (const int*)d_in[23];
    const int* edge_sid_neg = (const int*)d_in[24];
    const int* edge_qid_neg = (const int*)d_in[25];
    float* out = (float*)d_out;

    const int passA_smem = 2 * PA_WSM * sizeof(float);  // 35328 B -> 6 blocks/SM
    cudaFuncSetAttribute(k_passA, cudaFuncAttributeMaxDynamicSharedMemorySize, passA_smem);

    // 1: weight products + cursor zeroing
    k_init<<<128, 256>>>(W_fuse, W_K2, W_V2, b_fuse, b_V2);
    // 2: 7 prep GEMMs
    dim3 prepGrid(QN/128, 4, 7);
    k_prep<<<prepGrid, 128>>>(x, s_emb, W_Q, b_Q, W_K, b_K, W_V, b_V);
    // 3: s-side bucketing
    dim3 bGrid3(EN/256, 1, 2);
    k_bucket<<<bGrid3, 256>>>(edge_sid_pos, edge_qid_pos, edge_sid_neg, edge_qid_neg);
    // 4: hop-1 attention (tf32 HMMA, interleaved frag loads)
    dim3 aGrid(SN/2, 1, 2);
    k_passA<<<aGrid, 64, passA_smem>>>(hist_qid_pos, hist_cnt_pos,
                                       hist_qid_neg, hist_cnt_neg);
    // 5: hop-2 logits + segment softmax + finalize
    dim3 bGrid(QN/8, 1, 2);
    k_passB<<<bGrid, 256>>>(x);
    // 6: output projection
    k_project<<<QN/128, 128>>>(W_proj, b_proj, out);
}